// round 17
// baseline (speedup 1.0000x reference)
#include <cuda_runtime.h>
#include <cuda_bf16.h>
#include <cstdint>

// Problem constants
#define NN 10000
#define DD 256
#define HH 512
#define EE 320000

// Scratch (device globals: allocation-free rule; ~30MB proven-safe footprint)
__device__ float4 g_agg[NN * (DD / 4)];   // [N, 256]  aggregated messages
__device__ float4 g_h  [NN * (HH / 4)];   // [N, 512]  partials, then relu(cat@Wc+b)

// ---------------------------------------------------------------------------
// zero agg + seed out with b2 (merged)
__global__ void k_zero_init(float* __restrict__ out, const float* __restrict__ b2) {
    int i = blockIdx.x * blockDim.x + threadIdx.x;
    if (i < NN * (DD / 4)) g_agg[i] = make_float4(0.f, 0.f, 0.f, 0.f);
    if (i < NN) out[i] = b2[0];
}

// ---------------------------------------------------------------------------
// GEMM config (R14-proven: 128x128 tile, BK=16, 8x8/thread, packed f32x2)
#define BM 128
#define BN 128
#define BK 16
#define SCAT_CTAS 48
#define SCAT_WARPS (SCAT_CTAS * 8)

#define SPLAT64(dst, s)  asm("mov.b64 %0, {%1, %1};" : "=l"(dst) : "f"(s))
#define FMA2(acc, ap, bp) \
    asm("fma.rn.f32x2 %0, %1, %2, %0;" : "+l"(acc) : "l"(ap), "l"(bp))
#define UNPACK64(lo, hi, p) \
    asm("mov.b64 {%0, %1}, %2;" : "=f"(lo), "=f"(hi) : "l"(p))

// Shared GEMM-half body: C = A[N,256] @ Wc[kofs:kofs+256, :]
// mode 0: store raw partials to g_h;  mode 1: += partial + bias, relu, store.
__device__ __forceinline__ void gemm1_half_body(
    const float* __restrict__ A, const float* __restrict__ Wc,
    const float* __restrict__ bc, int kofs, int mode,
    int tileIdx) {
    __shared__ float As[BK][BM];
    __shared__ float Bs[BK][BN];

    const int tid = threadIdx.x;
    const int tx = tid & 15;
    const int ty = tid >> 4;
    const int rowBase = (tileIdx >> 2) * BM;   // 79 row tiles
    const int colBase = (tileIdx & 3) * BN;    // 4 col tiles

    const int la_row = tid >> 2;
    const int la_kc  = (tid & 3) * 4;
    const int lb_k   = tid >> 4;
    const int lb_nc  = (tid & 15) * 4;

    unsigned long long acc[8][4];
    #pragma unroll
    for (int i = 0; i < 8; i++)
        #pragma unroll
        for (int j = 0; j < 4; j++) acc[i][j] = 0ull;

    for (int kt = 0; kt < DD; kt += BK) {
        #pragma unroll
        for (int half = 0; half < 2; half++) {
            int gr = rowBase + la_row + half * 64;
            float4 a4 = make_float4(0.f, 0.f, 0.f, 0.f);
            if (gr < NN)
                a4 = *(const float4*)(A + (size_t)gr * DD + kt + la_kc);
            As[la_kc + 0][la_row + half * 64] = a4.x;
            As[la_kc + 1][la_row + half * 64] = a4.y;
            As[la_kc + 2][la_row + half * 64] = a4.z;
            As[la_kc + 3][la_row + half * 64] = a4.w;
        }
        #pragma unroll
        for (int half = 0; half < 2; half++) {
            float4 b4 = *(const float4*)(Wc + (size_t)(kofs + kt + lb_k) * HH + colBase + lb_nc + half * 64);
            *(float4*)&Bs[lb_k][lb_nc + half * 64] = b4;
        }
        __syncthreads();

        #pragma unroll
        for (int kk = 0; kk < BK; kk++) {
            float4 a0 = *(const float4*)&As[kk][ty * 4];
            float4 a1 = *(const float4*)&As[kk][64 + ty * 4];
            ulonglong2 bA = *(const ulonglong2*)&Bs[kk][tx * 4];
            ulonglong2 bB = *(const ulonglong2*)&Bs[kk][64 + tx * 4];
            float av[8] = {a0.x, a0.y, a0.z, a0.w, a1.x, a1.y, a1.z, a1.w};
            #pragma unroll
            for (int i = 0; i < 8; i++) {
                unsigned long long ap;
                SPLAT64(ap, av[i]);
                FMA2(acc[i][0], ap, bA.x);
                FMA2(acc[i][1], ap, bA.y);
                FMA2(acc[i][2], ap, bB.x);
                FMA2(acc[i][3], ap, bB.y);
            }
        }
        __syncthreads();
    }

    float* hf = (float*)g_h;
    if (mode == 0) {
        #pragma unroll
        for (int i = 0; i < 8; i++) {
            int r = rowBase + (i < 4 ? ty * 4 + i : 64 + ty * 4 + (i - 4));
            if (r < NN) {
                float c0, c1, c2, c3, c4, c5, c6, c7;
                UNPACK64(c0, c1, acc[i][0]);
                UNPACK64(c2, c3, acc[i][1]);
                UNPACK64(c4, c5, acc[i][2]);
                UNPACK64(c6, c7, acc[i][3]);
                *(float4*)(hf + (size_t)r * HH + colBase + tx * 4)      = make_float4(c0, c1, c2, c3);
                *(float4*)(hf + (size_t)r * HH + colBase + 64 + tx * 4) = make_float4(c4, c5, c6, c7);
            }
        }
    } else {
        const float4 bias0 = *(const float4*)(bc + colBase + tx * 4);
        const float4 bias1 = *(const float4*)(bc + colBase + 64 + tx * 4);
        #pragma unroll
        for (int i = 0; i < 8; i++) {
            int r = rowBase + (i < 4 ? ty * 4 + i : 64 + ty * 4 + (i - 4));
            if (r < NN) {
                float4 p0 = *(const float4*)(hf + (size_t)r * HH + colBase + tx * 4);
                float4 p1 = *(const float4*)(hf + (size_t)r * HH + colBase + 64 + tx * 4);
                float c0, c1, c2, c3, c4, c5, c6, c7;
                UNPACK64(c0, c1, acc[i][0]);
                UNPACK64(c2, c3, acc[i][1]);
                UNPACK64(c4, c5, acc[i][2]);
                UNPACK64(c6, c7, acc[i][3]);
                float4 o0, o1;
                o0.x = fmaxf(c0 + p0.x + bias0.x, 0.f);
                o0.y = fmaxf(c1 + p0.y + bias0.y, 0.f);
                o0.z = fmaxf(c2 + p0.z + bias0.z, 0.f);
                o0.w = fmaxf(c3 + p0.w + bias0.w, 0.f);
                o1.x = fmaxf(c4 + p1.x + bias1.x, 0.f);
                o1.y = fmaxf(c5 + p1.y + bias1.y, 0.f);
                o1.z = fmaxf(c6 + p1.z + bias1.z, 0.f);
                o1.w = fmaxf(c7 + p1.w + bias1.w, 0.f);
                *(float4*)(hf + (size_t)r * HH + colBase + tx * 4)      = o0;
                *(float4*)(hf + (size_t)r * HH + colBase + 64 + tx * 4) = o1;
            }
        }
    }
}

// ---------------------------------------------------------------------------
// Merged kernel: blocks [0, SCAT_CTAS) scatter edges (persistent warps, 4-edge
// ILP batches); blocks [SCAT_CTAS, SCAT_CTAS+316) run GEMM1a x-half tiles.
__global__ __launch_bounds__(256)
void k_scatter_gemm1a(const float4* __restrict__ x4,
                      const int*    __restrict__ esrc,
                      const int*    __restrict__ edst,
                      const float*  __restrict__ eval,
                      const float*  __restrict__ x,
                      const float*  __restrict__ Wc) {
    if (blockIdx.x < SCAT_CTAS) {
        // ---- scatter: agg[dst] += x[src] * val
        const int w    = blockIdx.x * 8 + (threadIdx.x >> 5);  // 0..SCAT_WARPS-1
        const int lane = threadIdx.x & 31;
        const int per  = (EE + SCAT_WARPS - 1) / SCAT_WARPS;
        int e    = w * per;
        int eEnd = e + per;
        if (eEnd > EE) eEnd = EE;

        // 4-edge ILP batches
        for (; e + 3 < eEnd; e += 4) {
            int   s0 = __ldg(esrc + e),     s1 = __ldg(esrc + e + 1);
            int   s2 = __ldg(esrc + e + 2), s3 = __ldg(esrc + e + 3);
            int   d0 = __ldg(edst + e),     d1 = __ldg(edst + e + 1);
            int   d2 = __ldg(edst + e + 2), d3 = __ldg(edst + e + 3);
            float v0 = __ldg(eval + e),     v1 = __ldg(eval + e + 1);
            float v2 = __ldg(eval + e + 2), v3 = __ldg(eval + e + 3);
            const float4* r0 = x4 + (size_t)s0 * (DD / 4);
            const float4* r1 = x4 + (size_t)s1 * (DD / 4);
            const float4* r2 = x4 + (size_t)s2 * (DD / 4);
            const float4* r3 = x4 + (size_t)s3 * (DD / 4);
            float4* a0 = g_agg + (size_t)d0 * (DD / 4);
            float4* a1 = g_agg + (size_t)d1 * (DD / 4);
            float4* a2 = g_agg + (size_t)d2 * (DD / 4);
            float4* a3 = g_agg + (size_t)d3 * (DD / 4);
            #pragma unroll
            for (int j = 0; j < 2; j++) {
                int c = lane + j * 32;
                float4 t0 = __ldg(r0 + c);
                float4 t1 = __ldg(r1 + c);
                float4 t2 = __ldg(r2 + c);
                float4 t3 = __ldg(r3 + c);
                t0.x *= v0; t0.y *= v0; t0.z *= v0; t0.w *= v0;
                t1.x *= v1; t1.y *= v1; t1.z *= v1; t1.w *= v1;
                t2.x *= v2; t2.y *= v2; t2.z *= v2; t2.w *= v2;
                t3.x *= v3; t3.y *= v3; t3.z *= v3; t3.w *= v3;
                atomicAdd(a0 + c, t0);
                atomicAdd(a1 + c, t1);
                atomicAdd(a2 + c, t2);
                atomicAdd(a3 + c, t3);
            }
        }
        // remainder
        for (; e < eEnd; e++) {
            int   s = __ldg(esrc + e);
            int   d = __ldg(edst + e);
            float v = __ldg(eval + e);
            const float4* xr = x4    + (size_t)s * (DD / 4);
            float4*       ar = g_agg + (size_t)d * (DD / 4);
            #pragma unroll
            for (int j = 0; j < 2; j++) {
                int c = lane + j * 32;
                float4 t = __ldg(xr + c);
                t.x *= v; t.y *= v; t.z *= v; t.w *= v;
                atomicAdd(ar + c, t);
            }
        }
    } else {
        // ---- GEMM1a: x-half, raw partials to g_h
        gemm1_half_body(x, Wc, nullptr, 0, 0, blockIdx.x - SCAT_CTAS);
    }
}

// GEMM1b: agg-half + partial + bias + relu
__global__ __launch_bounds__(256)
void k_gemm1b(const float* __restrict__ Wc, const float* __restrict__ bc) {
    gemm1_half_body((const float*)g_agg, Wc, bc, DD, 1, blockIdx.x);
}

// GEMM2 (fused head): z = prelu(h @ W1 + b1); out[r] += sum_c z[r,c]*W2[c]
__global__ __launch_bounds__(256)
void k_gemm2(const float* __restrict__ W1,
             const float* __restrict__ b1,
             const float* __restrict__ pa,
             const float* __restrict__ W2,
             float* __restrict__ out) {
    __shared__ float As[BK][BM];
    __shared__ float Bs[BK][BN];

    const int tid = threadIdx.x;
    const int tx = tid & 15;
    const int ty = tid >> 4;
    const int rowBase = blockIdx.y * BM;
    const int colBase = blockIdx.x * BN;

    const int la_row = tid >> 2;
    const int la_kc  = (tid & 3) * 4;
    const int lb_k   = tid >> 4;
    const int lb_nc  = (tid & 15) * 4;

    const float* hf = (const float*)g_h;

    unsigned long long acc[8][4];
    #pragma unroll
    for (int i = 0; i < 8; i++)
        #pragma unroll
        for (int j = 0; j < 4; j++) acc[i][j] = 0ull;

    for (int kt = 0; kt < HH; kt += BK) {
        #pragma unroll
        for (int half = 0; half < 2; half++) {
            int gr = rowBase + la_row + half * 64;
            float4 a4 = make_float4(0.f, 0.f, 0.f, 0.f);
            if (gr < NN)
                a4 = *(const float4*)(hf + (size_t)gr * HH + kt + la_kc);
            As[la_kc + 0][la_row + half * 64] = a4.x;
            As[la_kc + 1][la_row + half * 64] = a4.y;
            As[la_kc + 2][la_row + half * 64] = a4.z;
            As[la_kc + 3][la_row + half * 64] = a4.w;
        }
        #pragma unroll
        for (int half = 0; half < 2; half++) {
            float4 b4 = *(const float4*)(W1 + (size_t)(kt + lb_k) * HH + colBase + lb_nc + half * 64);
            *(float4*)&Bs[lb_k][lb_nc + half * 64] = b4;
        }
        __syncthreads();

        #pragma unroll
        for (int kk = 0; kk < BK; kk++) {
            float4 a0 = *(const float4*)&As[kk][ty * 4];
            float4 a1 = *(const float4*)&As[kk][64 + ty * 4];
            ulonglong2 bA = *(const ulonglong2*)&Bs[kk][tx * 4];
            ulonglong2 bB = *(const ulonglong2*)&Bs[kk][64 + tx * 4];
            float av[8] = {a0.x, a0.y, a0.z, a0.w, a1.x, a1.y, a1.z, a1.w};
            #pragma unroll
            for (int i = 0; i < 8; i++) {
                unsigned long long ap;
                SPLAT64(ap, av[i]);
                FMA2(acc[i][0], ap, bA.x);
                FMA2(acc[i][1], ap, bA.y);
                FMA2(acc[i][2], ap, bB.x);
                FMA2(acc[i][3], ap, bB.y);
            }
        }
        __syncthreads();
    }

    const float4 b1v0 = *(const float4*)(b1 + colBase + tx * 4);
    const float4 b1v1 = *(const float4*)(b1 + colBase + 64 + tx * 4);
    const float4 pav0 = *(const float4*)(pa + colBase + tx * 4);
    const float4 pav1 = *(const float4*)(pa + colBase + 64 + tx * 4);
    const float4 w2v0 = *(const float4*)(W2 + colBase + tx * 4);
    const float4 w2v1 = *(const float4*)(W2 + colBase + 64 + tx * 4);

    const float bz[8] = {b1v0.x, b1v0.y, b1v0.z, b1v0.w, b1v1.x, b1v1.y, b1v1.z, b1v1.w};
    const float pv[8] = {pav0.x, pav0.y, pav0.z, pav0.w, pav1.x, pav1.y, pav1.z, pav1.w};
    const float wv[8] = {w2v0.x, w2v0.y, w2v0.z, w2v0.w, w2v1.x, w2v1.y, w2v1.z, w2v1.w};

    #pragma unroll
    for (int i = 0; i < 8; i++) {
        float c[8];
        UNPACK64(c[0], c[1], acc[i][0]);
        UNPACK64(c[2], c[3], acc[i][1]);
        UNPACK64(c[4], c[5], acc[i][2]);
        UNPACK64(c[6], c[7], acc[i][3]);
        float s = 0.f;
        #pragma unroll
        for (int j = 0; j < 8; j++) {
            float z = c[j] + bz[j];
            z = z > 0.f ? z : pv[j] * z;
            s = fmaf(z, wv[j], s);
        }
        #pragma unroll
        for (int m = 8; m > 0; m >>= 1)
            s += __shfl_xor_sync(0xffffffffu, s, m);
        if (tx == 0) {
            int r = rowBase + (i < 4 ? ty * 4 + i : 64 + ty * 4 + (i - 4));
            if (r < NN) atomicAdd(out + r, s);
        }
    }
}

// ---------------------------------------------------------------------------
extern "C" void kernel_launch(void* const* d_in, const int* in_sizes, int n_in,
                              void* d_out, int out_size) {
    const float* x     = (const float*)d_in[0];
    const int*   esrc  = (const int*)  d_in[1];
    const int*   edst  = (const int*)  d_in[2];
    const float* eval  = (const float*)d_in[3];
    const float* Wc    = (const float*)d_in[4];
    const float* bc    = (const float*)d_in[5];
    const float* W1    = (const float*)d_in[6];
    const float* b1    = (const float*)d_in[7];
    const float* pa    = (const float*)d_in[8];
    const float* W2    = (const float*)d_in[9];
    const float* b2    = (const float*)d_in[10];
    float* out = (float*)d_out;

    const int NTILES = (HH / BN) * ((NN + BM - 1) / BM);   // 4 * 79 = 316

    // 1) zero agg + seed out
    k_zero_init<<<(NN * (DD / 4) + 255) / 256, 256>>>(out, b2);

    // 2) merged: scatter (blocks 0..47) + GEMM1a x-half (blocks 48..363)
    k_scatter_gemm1a<<<SCAT_CTAS + NTILES, 256>>>(
        (const float4*)x, esrc, edst, eval, x, Wc);

    // 3) GEMM1b: agg-half + partial + bias + relu
    k_gemm1b<<<NTILES, 256>>>(Wc, bc);

    // 4) GEMM2 fused with PReLU + W2 matvec head
    {
        dim3 grid(HH / BN, (NN + BM - 1) / BM);
        k_gemm2<<<grid, 256>>>(W1, b1, pa, W2, out);
    }
}